// round 14
// baseline (speedup 1.0000x reference)
#include <cuda_runtime.h>

// Problem constants
#define BATCH 16
#define H 1080
#define W 1920
#define OH (H - 6)   // 1074
#define OW (W - 6)   // 1914

// Tiling: 64 threads/CTA (2 warps). Warp spans 128 input cols (lane*4),
// emits 120 output cols. Vertical sums in packed f32x2 registers; horizontal
// 7-sums via 4 warp shuffles per quantity; dropped row re-loaded from L1.
// Algebra: (a) sigma1+sigma2 fused into one accumulated quantity vS;
// (b) scale-free formula — normalization (window[0]) cancels in the ratio.
// TH=27/TILESY=40 covers H exactly (27*40=1080): bottom tile (ty0=1053) runs
// 27 rows and emission lands exactly on [0, OH). 5120 blocks = 1.92 waves at
// 18 CTAs/SM (wave-2 fill 92%).
#define NTHREADS 64
#define WARP_OUT 120
#define CTA_OUT  240
#define TH 27
#define RH 33
#define TILESX 8              // 8*240 = 1920 >= 1914
#define TILESY 40             // 40*27 = 1080 == H
#define NBLOCKS (BATCH * TILESX * TILESY)  // 5120

#define C1_CONST 6.5025f
#define C2_CONST 58.5225f

typedef unsigned long long u64;

__device__ float g_part[NBLOCKS];
__device__ unsigned int g_count = 0;

// ---- f32x2 packed helpers (sm_103a) ----
__device__ __forceinline__ u64 pk(float lo, float hi) {
    u64 r; asm("mov.b64 %0, {%1, %2};" : "=l"(r) : "f"(lo), "f"(hi)); return r;
}
__device__ __forceinline__ void unpk(float& lo, float& hi, u64 v) {
    asm("mov.b64 {%0, %1}, %2;" : "=f"(lo), "=f"(hi) : "l"(v));
}
__device__ __forceinline__ u64 add2(u64 a, u64 b) {
    u64 r; asm("add.rn.f32x2 %0, %1, %2;" : "=l"(r) : "l"(a), "l"(b)); return r;
}
__device__ __forceinline__ u64 mul2(u64 a, u64 b) {
    u64 r; asm("mul.rn.f32x2 %0, %1, %2;" : "=l"(r) : "l"(a), "l"(b)); return r;
}
__device__ __forceinline__ u64 fma2(u64 a, u64 b, u64 c) {
    u64 r; asm("fma.rn.f32x2 %0, %1, %2, %3;" : "=l"(r) : "l"(a), "l"(b), "l"(c)); return r;
}

__global__ __launch_bounds__(NTHREADS, 18) void ssim_kernel(
    const float* __restrict__ img1,
    const float* __restrict__ img2,
    const float* __restrict__ window,
    float* __restrict__ out)
{
    __shared__ float  red[2];
    __shared__ double redd[2];
    __shared__ bool   is_last;

    const int bid = blockIdx.x;
    const int batch = bid / (TILESX * TILESY);
    const int rem = bid % (TILESX * TILESY);
    const int cx = rem % TILESX;
    const int ty0 = (rem / TILESX) * TH;

    const int t = threadIdx.x;
    const int lane = t & 31;
    const int warp = t >> 5;

    const int wx0 = cx * CTA_OUT + warp * WARP_OUT;
    int lc = wx0 + lane * 4;
    if (lc > W - 4) lc = W - 4;          // right-edge clamp (dup data gated off)

    // Scale-free constants: R = 1/window[0] (= 49 for the uniform window).
    const float R   = 1.0f / window[0];
    const float R2x = 2.0f * R;
    const float c1r = C1_CONST * R * R;
    const float c2r = C2_CONST * R * R;

    const int lb = lane * 4;
    bool okc[4];
    #pragma unroll
    for (int i = 0; i < 4; i++)
        okc[i] = (lb + i < WARP_OUT) && (wx0 + lb + i < OW);

    const float* __restrict__ pa = img1 + (size_t)batch * (H * W) + (size_t)ty0 * W + lc;
    const float* __restrict__ pb = img2 + (size_t)batch * (H * W) + (size_t)ty0 * W + lc;
    const int rmax = (H - ty0 < RH) ? (H - ty0) : RH;

    const u64 NEG1_2 = pk(-1.0f, -1.0f);

    // Packed vertical window sums: {col0,col1} / {col2,col3} per quantity.
    u64 v1p0 = 0, v1p1 = 0, v2p0 = 0, v2p1 = 0;
    u64 vSp0 = 0, vSp1 = 0, v12p0 = 0, v12p1 = 0;
    float acc = 0.f;

    float4 A = *(const float4*)pa;
    float4 B = *(const float4*)pb;

    #define ADDROW(X, Y)                                                     \
    {                                                                        \
        const u64 a0_ = pk((X).x, (X).y), a1_ = pk((X).z, (X).w);            \
        const u64 b0_ = pk((Y).x, (Y).y), b1_ = pk((Y).z, (Y).w);            \
        v1p0 = add2(v1p0, a0_);   v1p1 = add2(v1p1, a1_);                    \
        v2p0 = add2(v2p0, b0_);   v2p1 = add2(v2p1, b1_);                    \
        vSp0 = fma2(a0_, a0_, vSp0);  vSp0 = fma2(b0_, b0_, vSp0);           \
        vSp1 = fma2(a1_, a1_, vSp1);  vSp1 = fma2(b1_, b1_, vSp1);           \
        v12p0 = fma2(a0_, b0_, v12p0);  v12p1 = fma2(a1_, b1_, v12p1);       \
    }
    #define DROPROW()                                                        \
    {                                                                        \
        const float4 D1 = *(const float4*)(pa - 7 * W);                      \
        const float4 D2 = *(const float4*)(pb - 7 * W);                      \
        const u64 da0 = pk(D1.x, D1.y), da1 = pk(D1.z, D1.w);                \
        const u64 db0 = pk(D2.x, D2.y), db1 = pk(D2.z, D2.w);                \
        const u64 na0 = mul2(da0, NEG1_2), na1 = mul2(da1, NEG1_2);          \
        const u64 nb0 = mul2(db0, NEG1_2), nb1 = mul2(db1, NEG1_2);          \
        v1p0 = add2(v1p0, na0);   v1p1 = add2(v1p1, na1);                    \
        v2p0 = add2(v2p0, nb0);   v2p1 = add2(v2p1, nb1);                    \
        vSp0 = fma2(na0, da0, vSp0);  vSp0 = fma2(nb0, db0, vSp0);           \
        vSp1 = fma2(na1, da1, vSp1);  vSp1 = fma2(nb1, db1, vSp1);           \
        v12p0 = fma2(na0, db0, v12p0);  v12p1 = fma2(na1, db1, v12p1);       \
    }
    // Horizontal 7-sum: T = own 4-col total; Tn = next lane's total; slide.
    #define HSUM(q0, q1, wq)                                                 \
    {                                                                        \
        float x0_, x1_, x2_, x3_;                                            \
        unpk(x0_, x1_, q0); unpk(x2_, x3_, q1);                              \
        const float T_ = (x0_ + x1_) + (x2_ + x3_);                          \
        const float Tn_ = __shfl_down_sync(0xffffffffu, T_, 1);              \
        const float n3_ = __shfl_down_sync(0xffffffffu, x3_, 1);             \
        const float n4_ = __shfl_down_sync(0xffffffffu, x0_, 2);             \
        const float n5_ = __shfl_down_sync(0xffffffffu, x1_, 2);             \
        wq[0] = (T_ + Tn_) - n3_;                                            \
        wq[1] = wq[0] + (n3_ - x0_);                                         \
        wq[2] = wq[1] + (n4_ - x1_);                                         \
        wq[3] = wq[2] + (n5_ - x2_);                                         \
    }
    #define EMIT()                                                           \
    {                                                                        \
        float w1[4], w2[4], wS[4], w12[4];                                   \
        HSUM(v1p0, v1p1, w1)   HSUM(v2p0, v2p1, w2)                          \
        HSUM(vSp0, vSp1, wS)   HSUM(v12p0, v12p1, w12)                       \
        _Pragma("unroll")                                                    \
        for (int i_ = 0; i_ < 4; i_++) {                                     \
            if (okc[i_]) {                                                   \
                const float P_ = w1[i_] * w2[i_];                            \
                const float Q_ = fmaf(w2[i_], w2[i_], w1[i_] * w1[i_]);      \
                const float n1_ = fmaf(P_, 2.f, c1r);                        \
                const float t_  = fmaf(P_, -2.f, c2r);                       \
                const float n2_ = fmaf(w12[i_], R2x, t_);                    \
                const float d1_ = Q_ + c1r;                                  \
                const float d2_ = fmaf(wS[i_], R, c2r) - Q_;                 \
                acc += __fdividef(n1_ * n2_, d1_ * d2_);                     \
            }                                                                \
        }                                                                    \
    }

    // Prologue: rows 0..5 (accumulate only).
    #pragma unroll
    for (int r = 0; r < 6; r++) {
        const float4 An = *(const float4*)(pa + W);
        const float4 Bn = *(const float4*)(pb + W);
        ADDROW(A, B);
        A = An; B = Bn;
        pa += W; pb += W;
    }
    // Row 6: first emission (no drop yet).
    {
        const float4 An = *(const float4*)(pa + W);
        const float4 Bn = *(const float4*)(pb + W);
        ADDROW(A, B);
        EMIT();
        A = An; B = Bn;
        pa += W; pb += W;
    }
    // Steady state rows 7..TH-1.
    #pragma unroll 4
    for (int r = 7; r < TH; r++) {
        float4 An = A, Bn = B;
        if (r + 1 < rmax) {
            An = *(const float4*)(pa + W);
            Bn = *(const float4*)(pb + W);
        }
        ADDROW(A, B);
        DROPROW();
        EMIT();
        A = An; B = Bn;
        pa += W; pb += W;
    }
    // Rows TH..RH-1: all tiles except the bottom one.
    if (rmax == RH) {
        #pragma unroll
        for (int r = TH; r < RH; r++) {
            float4 An = A, Bn = B;
            if (r + 1 < RH) {   // compile-time under unroll
                An = *(const float4*)(pa + W);
                Bn = *(const float4*)(pb + W);
            }
            ADDROW(A, B);
            DROPROW();
            EMIT();
            A = An; B = Bn;
            pa += W; pb += W;
        }
    }
    #undef ADDROW
    #undef DROPROW
    #undef EMIT
    #undef HSUM

    // Block reduction (64 -> 2 -> 1).
    #pragma unroll
    for (int off = 16; off; off >>= 1)
        acc += __shfl_down_sync(0xffffffffu, acc, off);
    if (lane == 0) red[warp] = acc;
    __syncthreads();
    float blockAcc = 0.f;
    if (t == 0) blockAcc = red[0] + red[1];

    // Last-block final reduction.
    if (t == 0) {
        g_part[bid] = blockAcc;
        __threadfence();
        unsigned int prev = atomicAdd(&g_count, 1u);
        is_last = (prev == (unsigned int)(gridDim.x - 1));
    }
    __syncthreads();

    if (is_last) {
        double s = 0.0;
        for (int i = t; i < NBLOCKS; i += NTHREADS)
            s += (double)g_part[i];
        #pragma unroll
        for (int off = 16; off; off >>= 1)
            s += __shfl_down_sync(0xffffffffu, s, off);
        if (lane == 0) redd[warp] = s;
        __syncthreads();
        if (t == 0) {
            const double v = redd[0] + redd[1];
            out[0] = (float)(v / ((double)BATCH * OH * OW));
            g_count = 0;  // self-reset for next graph replay
        }
    }
}

extern "C" void kernel_launch(void* const* d_in, const int* in_sizes, int n_in,
                              void* d_out, int out_size) {
    const float* img1 = (const float*)d_in[0];
    const float* img2 = (const float*)d_in[1];
    const float* window = (const float*)d_in[2];
    float* out = (float*)d_out;

    ssim_kernel<<<NBLOCKS, NTHREADS>>>(img1, img2, window, out);
}

// round 15
// speedup vs baseline: 1.3070x; 1.3070x over previous
#include <cuda_runtime.h>

// Problem constants
#define BATCH 16
#define H 1080
#define W 1920
#define OH (H - 6)   // 1074
#define OW (W - 6)   // 1914

// Tiling: 64 threads/CTA (2 warps). Warp spans 128 input cols (lane*4),
// emits 120 output cols. Vertical sums in packed f32x2 registers; horizontal
// 7-sums via 4 warp shuffles per quantity; dropped row re-loaded from L1.
// Algebra: (a) sigma1+sigma2 fused into one accumulated quantity vS;
// (b) scale-free formula — normalization (window[0]) cancels in the ratio;
// (c) pairwise fraction combining halves the divide count.
// R14 lesson: occupancy is L1-capacity-capped (~15-16 CTAs of this shape);
// TH=30/RH=36 (R13 config) is the verified optimum.
#define NTHREADS 64
#define WARP_OUT 120
#define CTA_OUT  240
#define TH 30
#define RH 36
#define TILESX 8              // 8*240 = 1920 >= 1914
#define TILESY 36             // 36*30 = 1080 == H
#define NBLOCKS (BATCH * TILESX * TILESY)  // 4608

#define C1_CONST 6.5025f
#define C2_CONST 58.5225f

typedef unsigned long long u64;

__device__ float g_part[NBLOCKS];
__device__ unsigned int g_count = 0;

// ---- f32x2 packed helpers (sm_103a) ----
__device__ __forceinline__ u64 pk(float lo, float hi) {
    u64 r; asm("mov.b64 %0, {%1, %2};" : "=l"(r) : "f"(lo), "f"(hi)); return r;
}
__device__ __forceinline__ void unpk(float& lo, float& hi, u64 v) {
    asm("mov.b64 {%0, %1}, %2;" : "=f"(lo), "=f"(hi) : "l"(v));
}
__device__ __forceinline__ u64 add2(u64 a, u64 b) {
    u64 r; asm("add.rn.f32x2 %0, %1, %2;" : "=l"(r) : "l"(a), "l"(b)); return r;
}
__device__ __forceinline__ u64 mul2(u64 a, u64 b) {
    u64 r; asm("mul.rn.f32x2 %0, %1, %2;" : "=l"(r) : "l"(a), "l"(b)); return r;
}
__device__ __forceinline__ u64 fma2(u64 a, u64 b, u64 c) {
    u64 r; asm("fma.rn.f32x2 %0, %1, %2, %3;" : "=l"(r) : "l"(a), "l"(b), "l"(c)); return r;
}

__global__ __launch_bounds__(NTHREADS, 18) void ssim_kernel(
    const float* __restrict__ img1,
    const float* __restrict__ img2,
    const float* __restrict__ window,
    float* __restrict__ out)
{
    __shared__ float  red[2];
    __shared__ double redd[2];
    __shared__ bool   is_last;

    const int bid = blockIdx.x;
    const int batch = bid / (TILESX * TILESY);
    const int rem = bid % (TILESX * TILESY);
    const int cx = rem % TILESX;
    const int ty0 = (rem / TILESX) * TH;

    const int t = threadIdx.x;
    const int lane = t & 31;
    const int warp = t >> 5;

    const int wx0 = cx * CTA_OUT + warp * WARP_OUT;
    int lc = wx0 + lane * 4;
    if (lc > W - 4) lc = W - 4;          // right-edge clamp (dup data gated off)

    // Scale-free constants: R = 1/window[0] (= 49 for the uniform window).
    const float R   = 1.0f / window[0];
    const float R2x = 2.0f * R;
    const float c1r = C1_CONST * R * R;
    const float c2r = C2_CONST * R * R;

    const int lb = lane * 4;
    bool okc[4];
    #pragma unroll
    for (int i = 0; i < 4; i++)
        okc[i] = (lb + i < WARP_OUT) && (wx0 + lb + i < OW);

    const float* __restrict__ pa = img1 + (size_t)batch * (H * W) + (size_t)ty0 * W + lc;
    const float* __restrict__ pb = img2 + (size_t)batch * (H * W) + (size_t)ty0 * W + lc;
    const int rmax = (H - ty0 < RH) ? (H - ty0) : RH;

    const u64 NEG1_2 = pk(-1.0f, -1.0f);

    // Packed vertical window sums: {col0,col1} / {col2,col3} per quantity.
    u64 v1p0 = 0, v1p1 = 0, v2p0 = 0, v2p1 = 0;
    u64 vSp0 = 0, vSp1 = 0, v12p0 = 0, v12p1 = 0;
    float acc = 0.f;

    float4 A = *(const float4*)pa;
    float4 B = *(const float4*)pb;

    #define ADDROW(X, Y)                                                     \
    {                                                                        \
        const u64 a0_ = pk((X).x, (X).y), a1_ = pk((X).z, (X).w);            \
        const u64 b0_ = pk((Y).x, (Y).y), b1_ = pk((Y).z, (Y).w);            \
        v1p0 = add2(v1p0, a0_);   v1p1 = add2(v1p1, a1_);                    \
        v2p0 = add2(v2p0, b0_);   v2p1 = add2(v2p1, b1_);                    \
        vSp0 = fma2(a0_, a0_, vSp0);  vSp0 = fma2(b0_, b0_, vSp0);           \
        vSp1 = fma2(a1_, a1_, vSp1);  vSp1 = fma2(b1_, b1_, vSp1);           \
        v12p0 = fma2(a0_, b0_, v12p0);  v12p1 = fma2(a1_, b1_, v12p1);       \
    }
    #define DROPROW()                                                        \
    {                                                                        \
        const float4 D1 = *(const float4*)(pa - 7 * W);                      \
        const float4 D2 = *(const float4*)(pb - 7 * W);                      \
        const u64 da0 = pk(D1.x, D1.y), da1 = pk(D1.z, D1.w);                \
        const u64 db0 = pk(D2.x, D2.y), db1 = pk(D2.z, D2.w);                \
        const u64 na0 = mul2(da0, NEG1_2), na1 = mul2(da1, NEG1_2);          \
        const u64 nb0 = mul2(db0, NEG1_2), nb1 = mul2(db1, NEG1_2);          \
        v1p0 = add2(v1p0, na0);   v1p1 = add2(v1p1, na1);                    \
        v2p0 = add2(v2p0, nb0);   v2p1 = add2(v2p1, nb1);                    \
        vSp0 = fma2(na0, da0, vSp0);  vSp0 = fma2(nb0, db0, vSp0);           \
        vSp1 = fma2(na1, da1, vSp1);  vSp1 = fma2(nb1, db1, vSp1);           \
        v12p0 = fma2(na0, db0, v12p0);  v12p1 = fma2(na1, db1, v12p1);       \
    }
    // Horizontal 7-sum: T = own 4-col total; Tn = next lane's total; slide.
    #define HSUM(q0, q1, wq)                                                 \
    {                                                                        \
        float x0_, x1_, x2_, x3_;                                            \
        unpk(x0_, x1_, q0); unpk(x2_, x3_, q1);                              \
        const float T_ = (x0_ + x1_) + (x2_ + x3_);                          \
        const float Tn_ = __shfl_down_sync(0xffffffffu, T_, 1);              \
        const float n3_ = __shfl_down_sync(0xffffffffu, x3_, 1);             \
        const float n4_ = __shfl_down_sync(0xffffffffu, x0_, 2);             \
        const float n5_ = __shfl_down_sync(0xffffffffu, x1_, 2);             \
        wq[0] = (T_ + Tn_) - n3_;                                            \
        wq[1] = wq[0] + (n3_ - x0_);                                         \
        wq[2] = wq[1] + (n4_ - x1_);                                         \
        wq[3] = wq[2] + (n5_ - x2_);                                         \
    }
    #define EMIT()                                                           \
    {                                                                        \
        float w1[4], w2[4], wS[4], w12[4];                                   \
        HSUM(v1p0, v1p1, w1)   HSUM(v2p0, v2p1, w2)                          \
        HSUM(vSp0, vSp1, wS)   HSUM(v12p0, v12p1, w12)                       \
        float nm[4], dn[4];                                                  \
        _Pragma("unroll")                                                    \
        for (int i_ = 0; i_ < 4; i_++) {                                     \
            const float P_ = w1[i_] * w2[i_];                                \
            const float Q_ = fmaf(w2[i_], w2[i_], w1[i_] * w1[i_]);          \
            const float n1_ = fmaf(P_, 2.f, c1r);                            \
            const float t_  = fmaf(P_, -2.f, c2r);                           \
            const float n2_ = fmaf(w12[i_], R2x, t_);                        \
            const float d1_ = Q_ + c1r;                                      \
            const float d2_ = fmaf(wS[i_], R, c2r) - Q_;                     \
            nm[i_] = okc[i_] ? (n1_ * n2_) : 0.f;                            \
            dn[i_] = okc[i_] ? (d1_ * d2_) : 1.f;                            \
        }                                                                    \
        /* Pairwise fraction combine: 2 divides instead of 4. */             \
        acc += __fdividef(fmaf(nm[0], dn[1], nm[1] * dn[0]),                 \
                          dn[0] * dn[1]);                                    \
        acc += __fdividef(fmaf(nm[2], dn[3], nm[3] * dn[2]),                 \
                          dn[2] * dn[3]);                                    \
    }

    // Prologue: rows 0..5 (accumulate only).
    #pragma unroll
    for (int r = 0; r < 6; r++) {
        const float4 An = *(const float4*)(pa + W);
        const float4 Bn = *(const float4*)(pb + W);
        ADDROW(A, B);
        A = An; B = Bn;
        pa += W; pb += W;
    }
    // Row 6: first emission (no drop yet).
    {
        const float4 An = *(const float4*)(pa + W);
        const float4 Bn = *(const float4*)(pb + W);
        ADDROW(A, B);
        EMIT();
        A = An; B = Bn;
        pa += W; pb += W;
    }
    // Steady state rows 7..TH-1.
    #pragma unroll 4
    for (int r = 7; r < TH; r++) {
        float4 An = A, Bn = B;
        if (r + 1 < rmax) {
            An = *(const float4*)(pa + W);
            Bn = *(const float4*)(pb + W);
        }
        ADDROW(A, B);
        DROPROW();
        EMIT();
        A = An; B = Bn;
        pa += W; pb += W;
    }
    // Rows TH..RH-1: all tiles except the bottom one.
    if (rmax == RH) {
        #pragma unroll
        for (int r = TH; r < RH; r++) {
            float4 An = A, Bn = B;
            if (r + 1 < RH) {   // compile-time under unroll
                An = *(const float4*)(pa + W);
                Bn = *(const float4*)(pb + W);
            }
            ADDROW(A, B);
            DROPROW();
            EMIT();
            A = An; B = Bn;
            pa += W; pb += W;
        }
    }
    #undef ADDROW
    #undef DROPROW
    #undef EMIT
    #undef HSUM

    // Block reduction (64 -> 2 -> 1).
    #pragma unroll
    for (int off = 16; off; off >>= 1)
        acc += __shfl_down_sync(0xffffffffu, acc, off);
    if (lane == 0) red[warp] = acc;
    __syncthreads();
    float blockAcc = 0.f;
    if (t == 0) blockAcc = red[0] + red[1];

    // Last-block final reduction.
    if (t == 0) {
        g_part[bid] = blockAcc;
        __threadfence();
        unsigned int prev = atomicAdd(&g_count, 1u);
        is_last = (prev == (unsigned int)(gridDim.x - 1));
    }
    __syncthreads();

    if (is_last) {
        double s = 0.0;
        for (int i = t; i < NBLOCKS; i += NTHREADS)
            s += (double)g_part[i];
        #pragma unroll
        for (int off = 16; off; off >>= 1)
            s += __shfl_down_sync(0xffffffffu, s, off);
        if (lane == 0) redd[warp] = s;
        __syncthreads();
        if (t == 0) {
            const double v = redd[0] + redd[1];
            out[0] = (float)(v / ((double)BATCH * OH * OW));
            g_count = 0;  // self-reset for next graph replay
        }
    }
}

extern "C" void kernel_launch(void* const* d_in, const int* in_sizes, int n_in,
                              void* d_out, int out_size) {
    const float* img1 = (const float*)d_in[0];
    const float* img2 = (const float*)d_in[1];
    const float* window = (const float*)d_in[2];
    float* out = (float*)d_out;

    ssim_kernel<<<NBLOCKS, NTHREADS>>>(img1, img2, window, out);
}

// round 16
// speedup vs baseline: 1.3081x; 1.0008x over previous
#include <cuda_runtime.h>

// Problem constants
#define BATCH 16
#define H 1080
#define W 1920
#define OH (H - 6)   // 1074
#define OW (W - 6)   // 1914

// Tiling: 64 threads/CTA (2 warps). Warp spans 128 input cols (lane*4),
// emits 120 output cols. Vertical sums in packed f32x2 registers; horizontal
// 7-sums via 4 warp shuffles per quantity; dropped row re-loaded from L1
// with loads hoisted to the iteration top for latency cover.
// Algebra: sigma-sum fusion + scale-free formula + pairwise divides.
#define NTHREADS 64
#define WARP_OUT 120
#define CTA_OUT  240
#define TH 30
#define RH 36
#define TILESX 8              // 8*240 = 1920 >= 1914
#define TILESY 36             // 36*30 = 1080 == H
#define NBLOCKS (BATCH * TILESX * TILESY)  // 4608

#define C1_CONST 6.5025f
#define C2_CONST 58.5225f

typedef unsigned long long u64;

__device__ float g_part[NBLOCKS];
__device__ unsigned int g_count = 0;

// ---- f32x2 packed helpers (sm_103a) ----
__device__ __forceinline__ u64 pk(float lo, float hi) {
    u64 r; asm("mov.b64 %0, {%1, %2};" : "=l"(r) : "f"(lo), "f"(hi)); return r;
}
__device__ __forceinline__ void unpk(float& lo, float& hi, u64 v) {
    asm("mov.b64 {%0, %1}, %2;" : "=f"(lo), "=f"(hi) : "l"(v));
}
__device__ __forceinline__ u64 add2(u64 a, u64 b) {
    u64 r; asm("add.rn.f32x2 %0, %1, %2;" : "=l"(r) : "l"(a), "l"(b)); return r;
}
__device__ __forceinline__ u64 mul2(u64 a, u64 b) {
    u64 r; asm("mul.rn.f32x2 %0, %1, %2;" : "=l"(r) : "l"(a), "l"(b)); return r;
}
__device__ __forceinline__ u64 fma2(u64 a, u64 b, u64 c) {
    u64 r; asm("fma.rn.f32x2 %0, %1, %2, %3;" : "=l"(r) : "l"(a), "l"(b), "l"(c)); return r;
}

__global__ __launch_bounds__(NTHREADS, 18) void ssim_kernel(
    const float* __restrict__ img1,
    const float* __restrict__ img2,
    const float* __restrict__ window,
    float* __restrict__ out)
{
    __shared__ float  red[2];
    __shared__ double redd[2];
    __shared__ bool   is_last;

    const int bid = blockIdx.x;
    const int batch = bid / (TILESX * TILESY);
    const int rem = bid % (TILESX * TILESY);
    const int cx = rem % TILESX;
    const int ty0 = (rem / TILESX) * TH;

    const int t = threadIdx.x;
    const int lane = t & 31;
    const int warp = t >> 5;

    const int wx0 = cx * CTA_OUT + warp * WARP_OUT;
    int lc = wx0 + lane * 4;
    if (lc > W - 4) lc = W - 4;          // right-edge clamp (dup data gated off)

    // Scale-free constants: R = 1/window[0] (= 49 for the uniform window).
    const float R   = 1.0f / window[0];
    const float R2x = 2.0f * R;
    const float c1r = C1_CONST * R * R;
    const float c2r = C2_CONST * R * R;

    const int lb = lane * 4;
    bool okc[4];
    #pragma unroll
    for (int i = 0; i < 4; i++)
        okc[i] = (lb + i < WARP_OUT) && (wx0 + lb + i < OW);

    const float* __restrict__ pa = img1 + (size_t)batch * (H * W) + (size_t)ty0 * W + lc;
    const float* __restrict__ pb = img2 + (size_t)batch * (H * W) + (size_t)ty0 * W + lc;
    const int rmax = (H - ty0 < RH) ? (H - ty0) : RH;

    const u64 NEG1_2 = pk(-1.0f, -1.0f);

    // Packed vertical window sums: {col0,col1} / {col2,col3} per quantity.
    u64 v1p0 = 0, v1p1 = 0, v2p0 = 0, v2p1 = 0;
    u64 vSp0 = 0, vSp1 = 0, v12p0 = 0, v12p1 = 0;
    float acc0 = 0.f, acc1 = 0.f;

    float4 A = *(const float4*)pa;
    float4 B = *(const float4*)pb;

    #define ADDROW(X, Y)                                                     \
    {                                                                        \
        const u64 a0_ = pk((X).x, (X).y), a1_ = pk((X).z, (X).w);            \
        const u64 b0_ = pk((Y).x, (Y).y), b1_ = pk((Y).z, (Y).w);            \
        v1p0 = add2(v1p0, a0_);   v1p1 = add2(v1p1, a1_);                    \
        v2p0 = add2(v2p0, b0_);   v2p1 = add2(v2p1, b1_);                    \
        vSp0 = fma2(a0_, a0_, vSp0);  vSp0 = fma2(b0_, b0_, vSp0);           \
        vSp1 = fma2(a1_, a1_, vSp1);  vSp1 = fma2(b1_, b1_, vSp1);           \
        v12p0 = fma2(a0_, b0_, v12p0);  v12p1 = fma2(a1_, b1_, v12p1);       \
    }
    // Subtract a previously-loaded row (values already in registers).
    #define SUBROW(X, Y)                                                     \
    {                                                                        \
        const u64 da0 = pk((X).x, (X).y), da1 = pk((X).z, (X).w);            \
        const u64 db0 = pk((Y).x, (Y).y), db1 = pk((Y).z, (Y).w);            \
        const u64 na0 = mul2(da0, NEG1_2), na1 = mul2(da1, NEG1_2);          \
        const u64 nb0 = mul2(db0, NEG1_2), nb1 = mul2(db1, NEG1_2);          \
        v1p0 = add2(v1p0, na0);   v1p1 = add2(v1p1, na1);                    \
        v2p0 = add2(v2p0, nb0);   v2p1 = add2(v2p1, nb1);                    \
        vSp0 = fma2(na0, da0, vSp0);  vSp0 = fma2(nb0, db0, vSp0);           \
        vSp1 = fma2(na1, da1, vSp1);  vSp1 = fma2(nb1, db1, vSp1);           \
        v12p0 = fma2(na0, db0, v12p0);  v12p1 = fma2(na1, db1, v12p1);       \
    }
    // Horizontal 7-sum: T = own 4-col total; Tn = next lane's total; slide.
    #define HSUM(q0, q1, wq)                                                 \
    {                                                                        \
        float x0_, x1_, x2_, x3_;                                            \
        unpk(x0_, x1_, q0); unpk(x2_, x3_, q1);                              \
        const float T_ = (x0_ + x1_) + (x2_ + x3_);                          \
        const float Tn_ = __shfl_down_sync(0xffffffffu, T_, 1);              \
        const float n3_ = __shfl_down_sync(0xffffffffu, x3_, 1);             \
        const float n4_ = __shfl_down_sync(0xffffffffu, x0_, 2);             \
        const float n5_ = __shfl_down_sync(0xffffffffu, x1_, 2);             \
        wq[0] = (T_ + Tn_) - n3_;                                            \
        wq[1] = wq[0] + (n3_ - x0_);                                         \
        wq[2] = wq[1] + (n4_ - x1_);                                         \
        wq[3] = wq[2] + (n5_ - x2_);                                         \
    }
    #define EMIT()                                                           \
    {                                                                        \
        float w1[4], w2[4], wS[4], w12[4];                                   \
        HSUM(v1p0, v1p1, w1)   HSUM(v2p0, v2p1, w2)                          \
        HSUM(vSp0, vSp1, wS)   HSUM(v12p0, v12p1, w12)                       \
        float nm[4], dn[4];                                                  \
        _Pragma("unroll")                                                    \
        for (int i_ = 0; i_ < 4; i_++) {                                     \
            const float P_ = w1[i_] * w2[i_];                                \
            const float Q_ = fmaf(w2[i_], w2[i_], w1[i_] * w1[i_]);          \
            const float n1_ = fmaf(P_, 2.f, c1r);                            \
            const float t_  = fmaf(P_, -2.f, c2r);                           \
            const float n2_ = fmaf(w12[i_], R2x, t_);                        \
            const float d1_ = Q_ + c1r;                                      \
            const float d2_ = fmaf(wS[i_], R, c2r) - Q_;                     \
            nm[i_] = okc[i_] ? (n1_ * n2_) : 0.f;                            \
            dn[i_] = okc[i_] ? (d1_ * d2_) : 1.f;                            \
        }                                                                    \
        /* Pairwise fraction combine: 2 independent divides/accumulators. */ \
        acc0 += __fdividef(fmaf(nm[0], dn[1], nm[1] * dn[0]),                \
                           dn[0] * dn[1]);                                   \
        acc1 += __fdividef(fmaf(nm[2], dn[3], nm[3] * dn[2]),                \
                           dn[2] * dn[3]);                                   \
    }

    // Prologue: rows 0..5 (accumulate only).
    #pragma unroll
    for (int r = 0; r < 6; r++) {
        const float4 An = *(const float4*)(pa + W);
        const float4 Bn = *(const float4*)(pb + W);
        ADDROW(A, B);
        A = An; B = Bn;
        pa += W; pb += W;
    }
    // Row 6: first emission (no drop yet).
    {
        const float4 An = *(const float4*)(pa + W);
        const float4 Bn = *(const float4*)(pb + W);
        ADDROW(A, B);
        EMIT();
        A = An; B = Bn;
        pa += W; pb += W;
    }
    // Steady state rows 7..TH-1. All loads issued up front (MLP batch),
    // ADDROW (register-only) covers the drop-load latency before SUBROW.
    #pragma unroll 4
    for (int r = 7; r < TH; r++) {
        const float4 D1 = *(const float4*)(pa - 7 * W);
        const float4 D2 = *(const float4*)(pb - 7 * W);
        float4 An = A, Bn = B;
        if (r + 1 < rmax) {
            An = *(const float4*)(pa + W);
            Bn = *(const float4*)(pb + W);
        }
        ADDROW(A, B);
        SUBROW(D1, D2);
        EMIT();
        A = An; B = Bn;
        pa += W; pb += W;
    }
    // Rows TH..RH-1: all tiles except the bottom one.
    if (rmax == RH) {
        #pragma unroll
        for (int r = TH; r < RH; r++) {
            const float4 D1 = *(const float4*)(pa - 7 * W);
            const float4 D2 = *(const float4*)(pb - 7 * W);
            float4 An = A, Bn = B;
            if (r + 1 < RH) {   // compile-time under unroll
                An = *(const float4*)(pa + W);
                Bn = *(const float4*)(pb + W);
            }
            ADDROW(A, B);
            SUBROW(D1, D2);
            EMIT();
            A = An; B = Bn;
            pa += W; pb += W;
        }
    }
    #undef ADDROW
    #undef SUBROW
    #undef EMIT
    #undef HSUM

    // Block reduction (64 -> 2 -> 1).
    float acc = acc0 + acc1;
    #pragma unroll
    for (int off = 16; off; off >>= 1)
        acc += __shfl_down_sync(0xffffffffu, acc, off);
    if (lane == 0) red[warp] = acc;
    __syncthreads();
    float blockAcc = 0.f;
    if (t == 0) blockAcc = red[0] + red[1];

    // Last-block final reduction.
    if (t == 0) {
        g_part[bid] = blockAcc;
        __threadfence();
        unsigned int prev = atomicAdd(&g_count, 1u);
        is_last = (prev == (unsigned int)(gridDim.x - 1));
    }
    __syncthreads();

    if (is_last) {
        double s = 0.0;
        for (int i = t; i < NBLOCKS; i += NTHREADS)
            s += (double)g_part[i];
        #pragma unroll
        for (int off = 16; off; off >>= 1)
            s += __shfl_down_sync(0xffffffffu, s, off);
        if (lane == 0) redd[warp] = s;
        __syncthreads();
        if (t == 0) {
            const double v = redd[0] + redd[1];
            out[0] = (float)(v / ((double)BATCH * OH * OW));
            g_count = 0;  // self-reset for next graph replay
        }
    }
}

extern "C" void kernel_launch(void* const* d_in, const int* in_sizes, int n_in,
                              void* d_out, int out_size) {
    const float* img1 = (const float*)d_in[0];
    const float* img2 = (const float*)d_in[1];
    const float* window = (const float*)d_in[2];
    float* out = (float*)d_out;

    ssim_kernel<<<NBLOCKS, NTHREADS>>>(img1, img2, window, out);
}

// round 17
// speedup vs baseline: 1.3107x; 1.0020x over previous
#include <cuda_runtime.h>

// Problem constants
#define BATCH 16
#define H 1080
#define W 1920
#define OH (H - 6)   // 1074
#define OW (W - 6)   // 1914

// Tiling: 64 threads/CTA (2 warps). Warp spans 128 input cols (lane*4),
// emits 120 output cols. Vertical sums in packed f32x2 registers; horizontal
// 7-sums via 4 warp shuffles per quantity. Dropped row re-loaded via __ldcg
// (L2-cached, L1-bypass) one iteration ahead: L1 keeps only the 2 streaming
// rows, eliminating the 9-row/warp L1 capacity thrash.
#define NTHREADS 64
#define WARP_OUT 120
#define CTA_OUT  240
#define TH 30
#define RH 36
#define TILESX 8              // 8*240 = 1920 >= 1914
#define TILESY 36             // 36*30 = 1080 == H
#define NBLOCKS (BATCH * TILESX * TILESY)  // 4608

#define C1_CONST 6.5025f
#define C2_CONST 58.5225f

typedef unsigned long long u64;

__device__ float g_part[NBLOCKS];
__device__ unsigned int g_count = 0;

// ---- f32x2 packed helpers (sm_103a) ----
__device__ __forceinline__ u64 pk(float lo, float hi) {
    u64 r; asm("mov.b64 %0, {%1, %2};" : "=l"(r) : "f"(lo), "f"(hi)); return r;
}
__device__ __forceinline__ void unpk(float& lo, float& hi, u64 v) {
    asm("mov.b64 {%0, %1}, %2;" : "=f"(lo), "=f"(hi) : "l"(v));
}
__device__ __forceinline__ u64 add2(u64 a, u64 b) {
    u64 r; asm("add.rn.f32x2 %0, %1, %2;" : "=l"(r) : "l"(a), "l"(b)); return r;
}
__device__ __forceinline__ u64 mul2(u64 a, u64 b) {
    u64 r; asm("mul.rn.f32x2 %0, %1, %2;" : "=l"(r) : "l"(a), "l"(b)); return r;
}
__device__ __forceinline__ u64 fma2(u64 a, u64 b, u64 c) {
    u64 r; asm("fma.rn.f32x2 %0, %1, %2, %3;" : "=l"(r) : "l"(a), "l"(b), "l"(c)); return r;
}

__global__ __launch_bounds__(NTHREADS, 16) void ssim_kernel(
    const float* __restrict__ img1,
    const float* __restrict__ img2,
    const float* __restrict__ window,
    float* __restrict__ out)
{
    __shared__ float  red[2];
    __shared__ double redd[2];
    __shared__ bool   is_last;

    const int bid = blockIdx.x;
    const int batch = bid / (TILESX * TILESY);
    const int rem = bid % (TILESX * TILESY);
    const int cx = rem % TILESX;
    const int ty0 = (rem / TILESX) * TH;

    const int t = threadIdx.x;
    const int lane = t & 31;
    const int warp = t >> 5;

    const int wx0 = cx * CTA_OUT + warp * WARP_OUT;
    int lc = wx0 + lane * 4;
    if (lc > W - 4) lc = W - 4;          // right-edge clamp (dup data gated off)

    // Scale-free constants: R = 1/window[0] (= 49 for the uniform window).
    const float R   = 1.0f / window[0];
    const float R2x = 2.0f * R;
    const float c1r = C1_CONST * R * R;
    const float c2r = C2_CONST * R * R;

    const int lb = lane * 4;
    bool okc[4];
    #pragma unroll
    for (int i = 0; i < 4; i++)
        okc[i] = (lb + i < WARP_OUT) && (wx0 + lb + i < OW);

    const float* __restrict__ pa = img1 + (size_t)batch * (H * W) + (size_t)ty0 * W + lc;
    const float* __restrict__ pb = img2 + (size_t)batch * (H * W) + (size_t)ty0 * W + lc;
    const int rmax = (H - ty0 < RH) ? (H - ty0) : RH;

    const u64 NEG1_2 = pk(-1.0f, -1.0f);

    // Packed vertical window sums: {col0,col1} / {col2,col3} per quantity.
    u64 v1p0 = 0, v1p1 = 0, v2p0 = 0, v2p1 = 0;
    u64 vSp0 = 0, vSp1 = 0, v12p0 = 0, v12p1 = 0;
    float acc0 = 0.f, acc1 = 0.f;

    float4 A = *(const float4*)pa;
    float4 B = *(const float4*)pb;

    #define ADDROW(X, Y)                                                     \
    {                                                                        \
        const u64 a0_ = pk((X).x, (X).y), a1_ = pk((X).z, (X).w);            \
        const u64 b0_ = pk((Y).x, (Y).y), b1_ = pk((Y).z, (Y).w);            \
        v1p0 = add2(v1p0, a0_);   v1p1 = add2(v1p1, a1_);                    \
        v2p0 = add2(v2p0, b0_);   v2p1 = add2(v2p1, b1_);                    \
        vSp0 = fma2(a0_, a0_, vSp0);  vSp0 = fma2(b0_, b0_, vSp0);           \
        vSp1 = fma2(a1_, a1_, vSp1);  vSp1 = fma2(b1_, b1_, vSp1);           \
        v12p0 = fma2(a0_, b0_, v12p0);  v12p1 = fma2(a1_, b1_, v12p1);       \
    }
    // Subtract a previously-loaded row (values already in registers).
    #define SUBROW(X, Y)                                                     \
    {                                                                        \
        const u64 da0 = pk((X).x, (X).y), da1 = pk((X).z, (X).w);            \
        const u64 db0 = pk((Y).x, (Y).y), db1 = pk((Y).z, (Y).w);            \
        const u64 na0 = mul2(da0, NEG1_2), na1 = mul2(da1, NEG1_2);          \
        const u64 nb0 = mul2(db0, NEG1_2), nb1 = mul2(db1, NEG1_2);          \
        v1p0 = add2(v1p0, na0);   v1p1 = add2(v1p1, na1);                    \
        v2p0 = add2(v2p0, nb0);   v2p1 = add2(v2p1, nb1);                    \
        vSp0 = fma2(na0, da0, vSp0);  vSp0 = fma2(nb0, db0, vSp0);           \
        vSp1 = fma2(na1, da1, vSp1);  vSp1 = fma2(nb1, db1, vSp1);           \
        v12p0 = fma2(na0, db0, v12p0);  v12p1 = fma2(na1, db1, v12p1);       \
    }
    // Horizontal 7-sum: T = own 4-col total; Tn = next lane's total; slide.
    #define HSUM(q0, q1, wq)                                                 \
    {                                                                        \
        float x0_, x1_, x2_, x3_;                                            \
        unpk(x0_, x1_, q0); unpk(x2_, x3_, q1);                              \
        const float T_ = (x0_ + x1_) + (x2_ + x3_);                          \
        const float Tn_ = __shfl_down_sync(0xffffffffu, T_, 1);              \
        const float n3_ = __shfl_down_sync(0xffffffffu, x3_, 1);             \
        const float n4_ = __shfl_down_sync(0xffffffffu, x0_, 2);             \
        const float n5_ = __shfl_down_sync(0xffffffffu, x1_, 2);             \
        wq[0] = (T_ + Tn_) - n3_;                                            \
        wq[1] = wq[0] + (n3_ - x0_);                                         \
        wq[2] = wq[1] + (n4_ - x1_);                                         \
        wq[3] = wq[2] + (n5_ - x2_);                                         \
    }
    #define EMIT()                                                           \
    {                                                                        \
        float w1[4], w2[4], wS[4], w12[4];                                   \
        HSUM(v1p0, v1p1, w1)   HSUM(v2p0, v2p1, w2)                          \
        HSUM(vSp0, vSp1, wS)   HSUM(v12p0, v12p1, w12)                       \
        float nm[4], dn[4];                                                  \
        _Pragma("unroll")                                                    \
        for (int i_ = 0; i_ < 4; i_++) {                                     \
            const float P_ = w1[i_] * w2[i_];                                \
            const float Q_ = fmaf(w2[i_], w2[i_], w1[i_] * w1[i_]);          \
            const float n1_ = fmaf(P_, 2.f, c1r);                            \
            const float t_  = fmaf(P_, -2.f, c2r);                           \
            const float n2_ = fmaf(w12[i_], R2x, t_);                        \
            const float d1_ = Q_ + c1r;                                      \
            const float d2_ = fmaf(wS[i_], R, c2r) - Q_;                     \
            nm[i_] = okc[i_] ? (n1_ * n2_) : 0.f;                            \
            dn[i_] = d1_ * d2_;   /* d1,d2 > 0 always (Cauchy-Schwarz) */    \
        }                                                                    \
        acc0 += __fdividef(fmaf(nm[0], dn[1], nm[1] * dn[0]),                \
                           dn[0] * dn[1]);                                   \
        acc1 += __fdividef(fmaf(nm[2], dn[3], nm[3] * dn[2]),                \
                           dn[2] * dn[3]);                                   \
    }

    // Prologue: rows 0..5 (accumulate only).
    #pragma unroll
    for (int r = 0; r < 6; r++) {
        const float4 An = *(const float4*)(pa + W);
        const float4 Bn = *(const float4*)(pb + W);
        ADDROW(A, B);
        A = An; B = Bn;
        pa += W; pb += W;
    }
    // Row 6: first emission (no drop yet).
    {
        const float4 An = *(const float4*)(pa + W);
        const float4 Bn = *(const float4*)(pb + W);
        ADDROW(A, B);
        EMIT();
        A = An; B = Bn;
        pa += W; pb += W;
    }
    // Steady state rows 7..TH-1. Drop rows come via __ldcg (L2, L1-bypass),
    // prefetched ONE iteration ahead for latency cover.
    float4 D1 = __ldcg((const float4*)(pa - 7 * W));   // row 0, for r=7
    float4 D2 = __ldcg((const float4*)(pb - 7 * W));
    #pragma unroll 4
    for (int r = 7; r < TH; r++) {
        const float4 Dn1 = __ldcg((const float4*)(pa - 6 * W));  // row r-6, for r+1
        const float4 Dn2 = __ldcg((const float4*)(pb - 6 * W));
        float4 An = A, Bn = B;
        if (r + 1 < rmax) {
            An = *(const float4*)(pa + W);
            Bn = *(const float4*)(pb + W);
        }
        ADDROW(A, B);
        SUBROW(D1, D2);
        EMIT();
        A = An; B = Bn;
        D1 = Dn1; D2 = Dn2;
        pa += W; pb += W;
    }
    // Rows TH..RH-1: all tiles except the bottom one (D-chain continues).
    if (rmax == RH) {
        #pragma unroll
        for (int r = TH; r < RH; r++) {
            const float4 Dn1 = __ldcg((const float4*)(pa - 6 * W));
            const float4 Dn2 = __ldcg((const float4*)(pb - 6 * W));
            float4 An = A, Bn = B;
            if (r + 1 < RH) {   // compile-time under unroll
                An = *(const float4*)(pa + W);
                Bn = *(const float4*)(pb + W);
            }
            ADDROW(A, B);
            SUBROW(D1, D2);
            EMIT();
            A = An; B = Bn;
            D1 = Dn1; D2 = Dn2;
            pa += W; pb += W;
        }
    }
    #undef ADDROW
    #undef SUBROW
    #undef EMIT
    #undef HSUM

    // Block reduction (64 -> 2 -> 1).
    float acc = acc0 + acc1;
    #pragma unroll
    for (int off = 16; off; off >>= 1)
        acc += __shfl_down_sync(0xffffffffu, acc, off);
    if (lane == 0) red[warp] = acc;
    __syncthreads();
    float blockAcc = 0.f;
    if (t == 0) blockAcc = red[0] + red[1];

    // Last-block final reduction.
    if (t == 0) {
        g_part[bid] = blockAcc;
        __threadfence();
        unsigned int prev = atomicAdd(&g_count, 1u);
        is_last = (prev == (unsigned int)(gridDim.x - 1));
    }
    __syncthreads();

    if (is_last) {
        double s = 0.0;
        for (int i = t; i < NBLOCKS; i += NTHREADS)
            s += (double)g_part[i];
        #pragma unroll
        for (int off = 16; off; off >>= 1)
            s += __shfl_down_sync(0xffffffffu, s, off);
        if (lane == 0) redd[warp] = s;
        __syncthreads();
        if (t == 0) {
            const double v = redd[0] + redd[1];
            out[0] = (float)(v / ((double)BATCH * OH * OW));
            g_count = 0;  // self-reset for next graph replay
        }
    }
}

extern "C" void kernel_launch(void* const* d_in, const int* in_sizes, int n_in,
                              void* d_out, int out_size) {
    const float* img1 = (const float*)d_in[0];
    const float* img2 = (const float*)d_in[1];
    const float* window = (const float*)d_in[2];
    float* out = (float*)d_out;

    ssim_kernel<<<NBLOCKS, NTHREADS>>>(img1, img2, window, out);
}